// round 7
// baseline (speedup 1.0000x reference)
#include <cuda_runtime.h>
#include <cuda_fp16.h>
#include <cstdint>

// Problem constants: B=2, L=2048, D=1024, H=16, hd=64
#define BB 2
#define LL 2048
#define DD 1024
#define NH 16
#define HD 64
#define ML (BB*LL)          // 4096 rows

// fp16 scratch
static __device__ __half g_xh[ML*DD];
static __device__ __half g_Qh[ML*DD];
static __device__ __half g_Kh[ML*DD];
static __device__ __half g_Vh[ML*DD];
static __device__ __half g_Ah[ML*DD];
static __device__ __half g_Wh[4*DD*DD];

// ---------------------------------------------------------------------------
// helpers
// ---------------------------------------------------------------------------
__device__ __forceinline__ uint32_t smem_u32(const void* p) {
    uint32_t a;
    asm("{ .reg .u64 t; cvta.to.shared.u64 t, %1; cvt.u32.u64 %0, t; }" : "=r"(a) : "l"(p));
    return a;
}

#define CPA16(dst, src) \
    asm volatile("cp.async.cg.shared.global [%0], [%1], 16;" :: "r"(dst), "l"(src))
#define CP_COMMIT() asm volatile("cp.async.commit_group;" ::: "memory")
#define CP_WAIT(n)  asm volatile("cp.async.wait_group %0;" :: "n"(n) : "memory")

#define LDSM4(r0,r1,r2,r3, addr) \
    asm volatile("ldmatrix.sync.aligned.m8n8.x4.shared.b16 {%0,%1,%2,%3}, [%4];" \
        : "=r"(r0),"=r"(r1),"=r"(r2),"=r"(r3) : "r"(addr))

#define LDSM4T(r0,r1,r2,r3, addr) \
    asm volatile("ldmatrix.sync.aligned.m8n8.x4.trans.shared.b16 {%0,%1,%2,%3}, [%4];" \
        : "=r"(r0),"=r"(r1),"=r"(r2),"=r"(r3) : "r"(addr))

__device__ __forceinline__ void mma16(float* c, const uint32_t* a, uint32_t b0, uint32_t b1) {
    asm volatile("mma.sync.aligned.m16n8k16.row.col.f32.f16.f16.f32 "
        "{%0,%1,%2,%3}, {%4,%5,%6,%7}, {%8,%9}, {%0,%1,%2,%3};"
        : "+f"(c[0]), "+f"(c[1]), "+f"(c[2]), "+f"(c[3])
        : "r"(a[0]), "r"(a[1]), "r"(a[2]), "r"(a[3]), "r"(b0), "r"(b1));
}

// ---------------------------------------------------------------------------
// Fused f32 -> f16 conversion of x (4M elems) + 4 weights (1M each).
// 8 x 1M-element chunks; chunk = float4_idx >> 18.
// ---------------------------------------------------------------------------
__global__ void cvt_all(const float* __restrict__ x,
                        const float* __restrict__ Wq, const float* __restrict__ Wk,
                        const float* __restrict__ Wv, const float* __restrict__ Wo,
                        __half* __restrict__ xh, __half* __restrict__ Wh)
{
    int i = blockIdx.x * blockDim.x + threadIdx.x;     // float4 index, 0..2M-1
    int chunk = i >> 18;
    const float* in;
    __half* out;
    size_t base;
    if (chunk < 4) { in = x; out = xh; base = (size_t)i * 4; }
    else {
        int w = chunk - 4;
        in = (w == 0) ? Wq : (w == 1) ? Wk : (w == 2) ? Wv : Wo;
        out = Wh + (size_t)w * DD * DD;
        base = (size_t)(i & 0x3FFFF) * 4;
    }
    float4 v = *(const float4*)&in[base];
    __half2 h0 = __floats2half2_rn(v.x, v.y);
    __half2 h1 = __floats2half2_rn(v.z, v.w);
    *(uint2*)&out[base] = make_uint2(*(uint32_t*)&h0, *(uint32_t*)&h1);
}

// ---------------------------------------------------------------------------
// Pipelined FP16 GEMM: C[M,N] = A[M,K] @ W[N,K]^T, 128x128x32 tiles, 8 warps,
// cp.async 3-stage.  MODE 0: fused QKV, RoPE applied in epilogue for z<2,
// all outputs fp16.  MODE 1: f32 out (final projection).
// ---------------------------------------------------------------------------
#define BM 128
#define BN 128
#define BK 32
#define ALD 40
#define STAGE_B 20480
#define GEMM_SMEM (3*STAGE_B)

template<int MODE>
__global__ __launch_bounds__(256) void gemm_f16p(
    const __half* __restrict__ A,
    const __half* __restrict__ Wa, const __half* __restrict__ Wb, const __half* __restrict__ Wc,
    __half* __restrict__ Qh, __half* __restrict__ Kh, __half* __restrict__ Vh,
    float* __restrict__ Cfin, const float* __restrict__ freqs)
{
    const int z = blockIdx.z;
    const __half* W = (z == 0) ? Wa : (z == 1) ? Wb : Wc;

    extern __shared__ char smem[];
    const uint32_t s0 = smem_u32(smem);

    const int tid  = threadIdx.x;
    const int lane = tid & 31, warp = tid >> 5;
    const int g = lane >> 2, t = lane & 3;
    const int lrow = lane & 15, lko = (lane >> 4) * 8;
    const int wm = (warp & 3) * 32;
    const int wn = (warp >> 2) * 64;
    const int row0 = blockIdx.y * BM, col0 = blockIdx.x * BN;

    auto load_stage = [&](int st, int k0) {
        uint32_t base = s0 + st * STAGE_B;
        #pragma unroll
        for (int i = 0; i < 2; i++) {
            int cid = tid + i * 256;
            int r = cid >> 2, c4 = cid & 3;
            CPA16(base + r*80 + c4*16,         A + (size_t)(row0 + r) * DD + k0 + c4*8);
            CPA16(base + 10240 + r*80 + c4*16, W + (size_t)(col0 + r) * DD + k0 + c4*8);
        }
        CP_COMMIT();
    };

    float c[2][8][4] = {};

    load_stage(0, 0);
    load_stage(1, BK);

    for (int ch = 0; ch < DD/BK; ch++) {
        CP_WAIT(1);
        __syncthreads();
        if (ch + 2 < DD/BK) load_stage((ch + 2) % 3, (ch + 2) * BK);
        else CP_COMMIT();

        const uint32_t ab = s0 + (ch % 3) * STAGE_B;
        const uint32_t bb = ab + 10240;

        #pragma unroll
        for (int ks = 0; ks < 2; ks++) {
            const int kk = ks * 16;
            uint32_t af[2][4];
            #pragma unroll
            for (int mi = 0; mi < 2; mi++) {
                uint32_t ad = ab + (uint32_t)((wm + mi*16 + lrow) * ALD + kk + lko) * 2;
                LDSM4(af[mi][0], af[mi][1], af[mi][2], af[mi][3], ad);
            }
            #pragma unroll
            for (int n2 = 0; n2 < 4; n2++) {
                uint32_t r0, r1, r2, r3;
                uint32_t bd = bb + (uint32_t)((wn + n2*16 + lrow) * ALD + kk + lko) * 2;
                LDSM4(r0, r1, r2, r3, bd);
                #pragma unroll
                for (int mi = 0; mi < 2; mi++) {
                    mma16(c[mi][n2*2],   af[mi], r0, r2);
                    mma16(c[mi][n2*2+1], af[mi], r1, r3);
                }
            }
        }
        __syncthreads();
    }

    #pragma unroll
    for (int mi = 0; mi < 2; mi++) {
        int r = row0 + wm + mi * 16 + g;
        #pragma unroll
        for (int ni = 0; ni < 8; ni++) {
            int cc = col0 + wn + (ni >> 1) * 16 + (ni & 1) * 8 + t * 2;
            float v0 = c[mi][ni][0], v1 = c[mi][ni][1];
            float v2 = c[mi][ni][2], v3 = c[mi][ni][3];
            if (MODE == 1) {
                *(float2*)&Cfin[(size_t)r * DD + cc]       = make_float2(v0, v1);
                *(float2*)&Cfin[(size_t)(r + 8) * DD + cc] = make_float2(v2, v3);
            } else if (z == 2) {
                *(__half2*)&Vh[(size_t)r * DD + cc]       = __floats2half2_rn(v0, v1);
                *(__half2*)&Vh[(size_t)(r + 8) * DD + cc] = __floats2half2_rn(v2, v3);
            } else {
                // fused RoPE: (v0,v1) is an adjacent (even,odd) pair within a head
                __half* C = z ? Kh : Qh;
                int pp = (cc & (HD - 1)) >> 1;
                int l0 = r & (LL - 1), l1 = (r + 8) & (LL - 1);
                float2 f0 = *(const float2*)&freqs[(l0 * (HD/2) + pp) * 2];
                float2 f1 = *(const float2*)&freqs[(l1 * (HD/2) + pp) * 2];
                *(__half2*)&C[(size_t)r * DD + cc] =
                    __floats2half2_rn(v0*f0.x - v1*f0.y, v0*f0.y + v1*f0.x);
                *(__half2*)&C[(size_t)(r + 8) * DD + cc] =
                    __floats2half2_rn(v2*f1.x - v3*f1.y, v2*f1.y + v3*f1.x);
            }
        }
    }
}

// ---------------------------------------------------------------------------
// Flash attention (causal), fp16, q-tile 128 x kv-tile 64, cp.async double-
// buffered K/V. 8 warps as 4(rows)x2(cols): warp tile 32x32.
// ---------------------------------------------------------------------------
#define BQ 128
#define HLD 72
#define SLD 68
#define QH_ (BQ*HLD)               // halves in Q tile
#define KVH (64*HLD)               // halves per K or V buffer
#define FL_SMEM_BYTES ((QH_ + 4*KVH + BQ*HLD)*2 + BQ*SLD*4 + 3*BQ*4)

__global__ __launch_bounds__(256, 2) void flash_f16(
    const __half* __restrict__ Q, const __half* __restrict__ K,
    const __half* __restrict__ V, __half* __restrict__ O)
{
    extern __shared__ __half hsm[];
    __half* Qs = hsm;                              // [BQ][HLD]
    __half* Ps = hsm + QH_ + 4*KVH;                // [BQ][HLD]
    float*  Ss = (float*)(Ps + BQ*HLD);            // [BQ][SLD]
    float* m_s = Ss + BQ*SLD;
    float* l_s = m_s + BQ;
    float* a_s = l_s + BQ;

    const int tid = threadIdx.x;
    const int lane = tid & 31, warp = tid >> 5;
    const int g = lane >> 2, t = lane & 3;
    const int lrow = lane & 15, lko = (lane >> 4) * 8;
    const int wr = (warp & 3) * 32;      // q-row block (0/32/64/96)
    const int wc = (warp >> 2) * 32;     // col block (kv for S, hd for O)
    const int b = blockIdx.y >> 4, h = blockIdx.y & 15;
    const int q0 = blockIdx.x * BQ;
    const size_t headoff = (size_t)b * LL * DD + (size_t)h * HD;

    const uint32_t qsm  = smem_u32(Qs);
    const uint32_t ksm0 = qsm + QH_*2;
    const uint32_t vsm0 = qsm + (QH_ + 2*KVH)*2;
    const uint32_t psm  = qsm + (QH_ + 4*KVH)*2;

    auto issue_kv = [&](int kt, int buf) {
        const int kv0 = kt * 64;
        uint32_t kb = ksm0 + buf * KVH*2;
        uint32_t vb = vsm0 + buf * KVH*2;
        #pragma unroll
        for (int i = 0; i < 4; i++) {
            int cid = tid + i * 256;          // 0..1023
            int isv = cid >> 9;
            int cc  = cid & 511;
            int r = cc >> 3, c8 = cc & 7;
            const __half* src = (isv ? V : K) + headoff + (size_t)(kv0 + r) * DD + c8*8;
            CPA16((isv ? vb : kb) + r*144 + c8*16, src);
        }
    };

    // group 0: Q tile (128 rows) + kv tile 0
    #pragma unroll
    for (int i = 0; i < 4; i++) {
        int cid = tid + i * 256;              // 0..1023
        int r = cid >> 3, c8 = cid & 7;
        CPA16(qsm + r*144 + c8*16, Q + headoff + (size_t)(q0 + r) * DD + c8*8);
    }
    issue_kv(0, 0);
    CP_COMMIT();
    const int ntiles = 2 * blockIdx.x + 2;
    issue_kv(1, 1);
    CP_COMMIT();

    if (tid < BQ) { m_s[tid] = -1e30f; l_s[tid] = 0.f; }

    float acc[2][4][4] = {};

    for (int kt = 0; kt < ntiles; kt++) {
        const int kv0 = kt * 64;
        const uint32_t kb = ksm0 + (kt & 1) * KVH*2;
        const uint32_t vb = vsm0 + (kt & 1) * KVH*2;
        CP_WAIT(1);
        __syncthreads();

        // S = Q @ K^T  (warp: 32 x 32)
        float sfrag[2][4][4] = {};
        #pragma unroll
        for (int kk = 0; kk < HD; kk += 16) {
            uint32_t af[2][4];
            #pragma unroll
            for (int mi = 0; mi < 2; mi++)
                LDSM4(af[mi][0], af[mi][1], af[mi][2], af[mi][3],
                      qsm + (uint32_t)((wr + mi*16 + lrow) * HLD + kk + lko) * 2);
            #pragma unroll
            for (int n2 = 0; n2 < 2; n2++) {
                uint32_t r0, r1, r2, r3;
                LDSM4(r0, r1, r2, r3,
                      kb + (uint32_t)((wc + n2*16 + lrow) * HLD + kk + lko) * 2);
                #pragma unroll
                for (int mi = 0; mi < 2; mi++) {
                    mma16(sfrag[mi][n2*2],   af[mi], r0, r2);
                    mma16(sfrag[mi][n2*2+1], af[mi], r1, r3);
                }
            }
        }
        const bool diag = (kt >= ntiles - 2);
        #pragma unroll
        for (int mi = 0; mi < 2; mi++) {
            #pragma unroll
            for (int ni = 0; ni < 4; ni++) {
                int r0r = wr + mi*16 + g, r1 = r0r + 8;
                int cc = wc + (ni >> 1) * 16 + (ni & 1) * 8 + t * 2;
                float v0 = sfrag[mi][ni][0]*0.125f, v1 = sfrag[mi][ni][1]*0.125f;
                float v2 = sfrag[mi][ni][2]*0.125f, v3 = sfrag[mi][ni][3]*0.125f;
                if (diag) {
                    int gr0 = q0 + r0r, gr1 = q0 + r1, gc = kv0 + cc;
                    if (gc     > gr0) v0 = -1e30f;
                    if (gc + 1 > gr0) v1 = -1e30f;
                    if (gc     > gr1) v2 = -1e30f;
                    if (gc + 1 > gr1) v3 = -1e30f;
                }
                *(float2*)&Ss[r0r*SLD + cc] = make_float2(v0, v1);
                *(float2*)&Ss[r1*SLD + cc]  = make_float2(v2, v3);
            }
        }
        __syncthreads();

        // online softmax: 2 threads per row (32 contiguous cols each); P -> fp16
        {
            int r = tid >> 1, hf = tid & 1;
            int cb = hf * 32;
            float mold = m_s[r];
            float mx = mold;
            #pragma unroll
            for (int j = 0; j < 32; j++) mx = fmaxf(mx, Ss[r*SLD + cb + j]);
            mx = fmaxf(mx, __shfl_xor_sync(0xffffffffu, mx, 1));
            float sum = 0.f;
            #pragma unroll
            for (int j = 0; j < 32; j++) {
                float p = __expf(Ss[r*SLD + cb + j] - mx);
                sum += p;
                Ps[r*HLD + cb + j] = __float2half_rn(p);
            }
            sum += __shfl_xor_sync(0xffffffffu, sum, 1);
            if (hf == 0) {
                float alpha = __expf(mold - mx);
                l_s[r] = l_s[r] * alpha + sum;
                m_s[r] = mx;
                a_s[r] = alpha;
            }
        }
        __syncthreads();

        // O = O*alpha + P @ V
        #pragma unroll
        for (int mi = 0; mi < 2; mi++) {
            float al0 = a_s[wr + mi*16 + g], al1 = a_s[wr + mi*16 + g + 8];
            #pragma unroll
            for (int ni = 0; ni < 4; ni++) {
                acc[mi][ni][0] *= al0; acc[mi][ni][1] *= al0;
                acc[mi][ni][2] *= al1; acc[mi][ni][3] *= al1;
            }
        }
        #pragma unroll
        for (int kk = 0; kk < 64; kk += 16) {
            uint32_t af[2][4];
            #pragma unroll
            for (int mi = 0; mi < 2; mi++)
                LDSM4(af[mi][0], af[mi][1], af[mi][2], af[mi][3],
                      psm + (uint32_t)((wr + mi*16 + lrow) * HLD + kk + lko) * 2);
            #pragma unroll
            for (int n2 = 0; n2 < 2; n2++) {
                uint32_t r0, r1, r2, r3;   // trans: rows = kv, cols = hd
                LDSM4T(r0, r1, r2, r3,
                       vb + (uint32_t)((kk + lrow) * HLD + wc + n2*16 + lko) * 2);
                #pragma unroll
                for (int mi = 0; mi < 2; mi++) {
                    mma16(acc[mi][n2*2],   af[mi], r0, r1);
                    mma16(acc[mi][n2*2+1], af[mi], r2, r3);
                }
            }
        }
        __syncthreads();
        if (kt + 2 < ntiles) issue_kv(kt + 2, kt & 1);
        CP_COMMIT();
    }

    // epilogue (fp16 out)
    #pragma unroll
    for (int mi = 0; mi < 2; mi++) {
        int r0r = wr + mi*16 + g, r1 = r0r + 8;
        float inv0 = 1.f / l_s[r0r], inv1 = 1.f / l_s[r1];
        #pragma unroll
        for (int ni = 0; ni < 4; ni++) {
            int cc = wc + (ni >> 1) * 16 + (ni & 1) * 8 + t * 2;
            *(__half2*)&O[headoff + (size_t)(q0 + r0r)*DD + cc] =
                __floats2half2_rn(acc[mi][ni][0]*inv0, acc[mi][ni][1]*inv0);
            *(__half2*)&O[headoff + (size_t)(q0 + r1)*DD + cc] =
                __floats2half2_rn(acc[mi][ni][2]*inv1, acc[mi][ni][3]*inv1);
        }
    }
}

// ---------------------------------------------------------------------------
extern "C" void kernel_launch(void* const* d_in, const int* in_sizes, int n_in,
                              void* d_out, int out_size)
{
    const float* x     = (const float*)d_in[0];
    const float* freqs = (const float*)d_in[1];
    // d_in[2] = attention_mask (pure causal; handled structurally)
    const float* Wq = (const float*)d_in[3];
    const float* Wk = (const float*)d_in[4];
    const float* Wv = (const float*)d_in[5];
    const float* Wo = (const float*)d_in[6];
    float* out = (float*)d_out;

    __half *pxh, *pQh, *pKh, *pVh, *pAh, *pWh;
    cudaGetSymbolAddress((void**)&pxh, g_xh);
    cudaGetSymbolAddress((void**)&pQh, g_Qh);
    cudaGetSymbolAddress((void**)&pKh, g_Kh);
    cudaGetSymbolAddress((void**)&pVh, g_Vh);
    cudaGetSymbolAddress((void**)&pAh, g_Ah);
    cudaGetSymbolAddress((void**)&pWh, g_Wh);

    // fused f32 -> f16 conversions (x + 4 weights)
    cvt_all<<<(2*ML*DD/4)/256, 256>>>(x, Wq, Wk, Wv, Wo, pxh, pWh);

    cudaFuncSetAttribute(gemm_f16p<0>, cudaFuncAttributeMaxDynamicSharedMemorySize, GEMM_SMEM);
    cudaFuncSetAttribute(gemm_f16p<1>, cudaFuncAttributeMaxDynamicSharedMemorySize, GEMM_SMEM);

    // Fused QKV projections with RoPE in epilogue (z0->Qh, z1->Kh, z2->Vh)
    gemm_f16p<0><<<dim3(DD/BN, ML/BM, 3), 256, GEMM_SMEM>>>(
        pxh, pWh, pWh + DD*DD, pWh + 2*DD*DD, pQh, pKh, pVh, nullptr, freqs);

    cudaFuncSetAttribute(flash_f16, cudaFuncAttributeMaxDynamicSharedMemorySize, FL_SMEM_BYTES);
    flash_f16<<<dim3(LL/BQ, BB*NH), 256, FL_SMEM_BYTES>>>(pQh, pKh, pVh, pAh);

    // Output projection: f16 A @ Wo^T -> f32 out
    gemm_f16p<1><<<dim3(DD/BN, ML/BM, 1), 256, GEMM_SMEM>>>(
        pAh, pWh + 3*DD*DD, nullptr, nullptr, nullptr, nullptr, nullptr, out, nullptr);
}

// round 8
// speedup vs baseline: 1.1825x; 1.1825x over previous
#include <cuda_runtime.h>
#include <cuda_fp16.h>
#include <cstdint>

// Problem constants: B=2, L=2048, D=1024, H=16, hd=64
#define BB 2
#define LL 2048
#define DD 1024
#define NH 16
#define HD 64
#define ML (BB*LL)          // 4096 rows

// fp16 scratch
static __device__ __half g_xh[ML*DD];
static __device__ __half g_Qh[ML*DD];
static __device__ __half g_Kh[ML*DD];
static __device__ __half g_Vh[ML*DD];
static __device__ __half g_Ah[ML*DD];
static __device__ __half g_Wh[4*DD*DD];

// ---------------------------------------------------------------------------
// helpers
// ---------------------------------------------------------------------------
__device__ __forceinline__ uint32_t smem_u32(const void* p) {
    uint32_t a;
    asm("{ .reg .u64 t; cvta.to.shared.u64 t, %1; cvt.u32.u64 %0, t; }" : "=r"(a) : "l"(p));
    return a;
}

#define CPA16(dst, src) \
    asm volatile("cp.async.cg.shared.global [%0], [%1], 16;" :: "r"(dst), "l"(src))
#define CP_COMMIT() asm volatile("cp.async.commit_group;" ::: "memory")
#define CP_WAIT(n)  asm volatile("cp.async.wait_group %0;" :: "n"(n) : "memory")

#define LDSM4(r0,r1,r2,r3, addr) \
    asm volatile("ldmatrix.sync.aligned.m8n8.x4.shared.b16 {%0,%1,%2,%3}, [%4];" \
        : "=r"(r0),"=r"(r1),"=r"(r2),"=r"(r3) : "r"(addr))

#define LDSM4T(r0,r1,r2,r3, addr) \
    asm volatile("ldmatrix.sync.aligned.m8n8.x4.trans.shared.b16 {%0,%1,%2,%3}, [%4];" \
        : "=r"(r0),"=r"(r1),"=r"(r2),"=r"(r3) : "r"(addr))

__device__ __forceinline__ void mma16(float* c, const uint32_t* a, uint32_t b0, uint32_t b1) {
    asm volatile("mma.sync.aligned.m16n8k16.row.col.f32.f16.f16.f32 "
        "{%0,%1,%2,%3}, {%4,%5,%6,%7}, {%8,%9}, {%0,%1,%2,%3};"
        : "+f"(c[0]), "+f"(c[1]), "+f"(c[2]), "+f"(c[3])
        : "r"(a[0]), "r"(a[1]), "r"(a[2]), "r"(a[3]), "r"(b0), "r"(b1));
}

// ---------------------------------------------------------------------------
// Fused f32 -> f16 conversion of x (4M elems) + 4 weights (1M each).
// ---------------------------------------------------------------------------
__global__ void cvt_all(const float* __restrict__ x,
                        const float* __restrict__ Wq, const float* __restrict__ Wk,
                        const float* __restrict__ Wv, const float* __restrict__ Wo,
                        __half* __restrict__ xh, __half* __restrict__ Wh)
{
    int i = blockIdx.x * blockDim.x + threadIdx.x;     // float4 index, 0..2M-1
    int chunk = i >> 18;
    const float* in;
    __half* out;
    size_t base;
    if (chunk < 4) { in = x; out = xh; base = (size_t)i * 4; }
    else {
        int w = chunk - 4;
        in = (w == 0) ? Wq : (w == 1) ? Wk : (w == 2) ? Wv : Wo;
        out = Wh + (size_t)w * DD * DD;
        base = (size_t)(i & 0x3FFFF) * 4;
    }
    float4 v = *(const float4*)&in[base];
    __half2 h0 = __floats2half2_rn(v.x, v.y);
    __half2 h1 = __floats2half2_rn(v.z, v.w);
    *(uint2*)&out[base] = make_uint2(*(uint32_t*)&h0, *(uint32_t*)&h1);
}

// ---------------------------------------------------------------------------
// Pipelined FP16 GEMM: C[M,N] = A[M,K] @ W[N,K]^T, 128x128x32 tiles, 8 warps,
// cp.async 3-stage.  MODE 0: fused QKV, RoPE applied in epilogue for z<2,
// all outputs fp16.  MODE 1: f32 out (final projection).
// ---------------------------------------------------------------------------
#define BM 128
#define BN 128
#define BK 32
#define ALD 40
#define STAGE_B 20480
#define GEMM_SMEM (3*STAGE_B)

template<int MODE>
__global__ __launch_bounds__(256) void gemm_f16p(
    const __half* __restrict__ A,
    const __half* __restrict__ Wa, const __half* __restrict__ Wb, const __half* __restrict__ Wc,
    __half* __restrict__ Qh, __half* __restrict__ Kh, __half* __restrict__ Vh,
    float* __restrict__ Cfin, const float* __restrict__ freqs)
{
    const int z = blockIdx.z;
    const __half* W = (z == 0) ? Wa : (z == 1) ? Wb : Wc;

    extern __shared__ char smem[];
    const uint32_t s0 = smem_u32(smem);

    const int tid  = threadIdx.x;
    const int lane = tid & 31, warp = tid >> 5;
    const int g = lane >> 2, t = lane & 3;
    const int lrow = lane & 15, lko = (lane >> 4) * 8;
    const int wm = (warp & 3) * 32;
    const int wn = (warp >> 2) * 64;
    const int row0 = blockIdx.y * BM, col0 = blockIdx.x * BN;

    auto load_stage = [&](int st, int k0) {
        uint32_t base = s0 + st * STAGE_B;
        #pragma unroll
        for (int i = 0; i < 2; i++) {
            int cid = tid + i * 256;
            int r = cid >> 2, c4 = cid & 3;
            CPA16(base + r*80 + c4*16,         A + (size_t)(row0 + r) * DD + k0 + c4*8);
            CPA16(base + 10240 + r*80 + c4*16, W + (size_t)(col0 + r) * DD + k0 + c4*8);
        }
        CP_COMMIT();
    };

    float c[2][8][4] = {};

    load_stage(0, 0);
    load_stage(1, BK);

    for (int ch = 0; ch < DD/BK; ch++) {
        CP_WAIT(1);
        __syncthreads();
        if (ch + 2 < DD/BK) load_stage((ch + 2) % 3, (ch + 2) * BK);
        else CP_COMMIT();

        const uint32_t ab = s0 + (ch % 3) * STAGE_B;
        const uint32_t bb = ab + 10240;

        #pragma unroll
        for (int ks = 0; ks < 2; ks++) {
            const int kk = ks * 16;
            uint32_t af[2][4];
            #pragma unroll
            for (int mi = 0; mi < 2; mi++) {
                uint32_t ad = ab + (uint32_t)((wm + mi*16 + lrow) * ALD + kk + lko) * 2;
                LDSM4(af[mi][0], af[mi][1], af[mi][2], af[mi][3], ad);
            }
            #pragma unroll
            for (int n2 = 0; n2 < 4; n2++) {
                uint32_t r0, r1, r2, r3;
                uint32_t bd = bb + (uint32_t)((wn + n2*16 + lrow) * ALD + kk + lko) * 2;
                LDSM4(r0, r1, r2, r3, bd);
                #pragma unroll
                for (int mi = 0; mi < 2; mi++) {
                    mma16(c[mi][n2*2],   af[mi], r0, r2);
                    mma16(c[mi][n2*2+1], af[mi], r1, r3);
                }
            }
        }
        __syncthreads();
    }

    #pragma unroll
    for (int mi = 0; mi < 2; mi++) {
        int r = row0 + wm + mi * 16 + g;
        #pragma unroll
        for (int ni = 0; ni < 8; ni++) {
            int cc = col0 + wn + (ni >> 1) * 16 + (ni & 1) * 8 + t * 2;
            float v0 = c[mi][ni][0], v1 = c[mi][ni][1];
            float v2 = c[mi][ni][2], v3 = c[mi][ni][3];
            if (MODE == 1) {
                *(float2*)&Cfin[(size_t)r * DD + cc]       = make_float2(v0, v1);
                *(float2*)&Cfin[(size_t)(r + 8) * DD + cc] = make_float2(v2, v3);
            } else if (z == 2) {
                *(__half2*)&Vh[(size_t)r * DD + cc]       = __floats2half2_rn(v0, v1);
                *(__half2*)&Vh[(size_t)(r + 8) * DD + cc] = __floats2half2_rn(v2, v3);
            } else {
                // fused RoPE: (v0,v1) is an adjacent (even,odd) pair within a head
                __half* C = z ? Kh : Qh;
                int pp = (cc & (HD - 1)) >> 1;
                int l0 = r & (LL - 1), l1 = (r + 8) & (LL - 1);
                float2 f0 = *(const float2*)&freqs[(l0 * (HD/2) + pp) * 2];
                float2 f1 = *(const float2*)&freqs[(l1 * (HD/2) + pp) * 2];
                *(__half2*)&C[(size_t)r * DD + cc] =
                    __floats2half2_rn(v0*f0.x - v1*f0.y, v0*f0.y + v1*f0.x);
                *(__half2*)&C[(size_t)(r + 8) * DD + cc] =
                    __floats2half2_rn(v2*f1.x - v3*f1.y, v2*f1.y + v3*f1.x);
            }
        }
    }
}

// ---------------------------------------------------------------------------
// Flash attention (causal), fp16, q-tile 64 x kv-tile 64 (R6-proven shape),
// cp.async double-buffered K/V. 8 warps: wr=(warp&3)*16, wc=(warp>>2)*32.
// Heavy blocks (large ntiles) scheduled first via blockIdx remap.
// ---------------------------------------------------------------------------
#define HLD 72
#define SLD 68
#define KVH (64*HLD)                  // halves per K or V buffer
#define FL_SMEM_BYTES (6*KVH*2 + 64*SLD*4 + 3*64*4)

__global__ __launch_bounds__(256) void flash_f16(
    const __half* __restrict__ Q, const __half* __restrict__ K,
    const __half* __restrict__ V, __half* __restrict__ O)
{
    extern __shared__ __half hsm[];
    __half* Qs = hsm;                         // [64][HLD]
    __half* Ps = hsm + 5*KVH;
    float*  Ss = (float*)(hsm + 6*KVH);       // [64][SLD]
    float* m_s = Ss + 64*SLD;
    float* l_s = m_s + 64;
    float* a_s = l_s + 64;

    const int tid = threadIdx.x;
    const int lane = tid & 31, warp = tid >> 5;
    const int g = lane >> 2, t = lane & 3;
    const int lrow = lane & 15, lko = (lane >> 4) * 8;
    const int wr = (warp & 3) * 16;
    const int wc = (warp >> 2) * 32;
    const int b = blockIdx.y >> 4, h = blockIdx.y & 15;
    const int qi = (int)gridDim.x - 1 - (int)blockIdx.x;   // heavy blocks first
    const int q0 = qi * 64;
    const size_t headoff = (size_t)b * LL * DD + (size_t)h * HD;

    const uint32_t qsm = smem_u32(Qs);
    const uint32_t ksm0 = qsm + KVH*2;
    const uint32_t vsm0 = qsm + 3*KVH*2;
    const uint32_t psm = qsm + 5*KVH*2;

    auto issue_kv = [&](int kt, int buf) {
        const int kv0 = kt * 64;
        uint32_t kb = ksm0 + buf * KVH*2;
        uint32_t vb = vsm0 + buf * KVH*2;
        #pragma unroll
        for (int i = 0; i < 4; i++) {
            int cid = tid + i * 256;          // 0..1023
            int isv = cid >> 9;
            int cc  = cid & 511;
            int r = cc >> 3, c8 = cc & 7;
            const __half* src = (isv ? V : K) + headoff + (size_t)(kv0 + r) * DD + c8*8;
            CPA16((isv ? vb : kb) + r*144 + c8*16, src);
        }
    };

    // group 0: Q tile + kv tile 0
    #pragma unroll
    for (int i = 0; i < 2; i++) {
        int cid = tid + i * 256;
        int r = cid >> 3, c8 = cid & 7;
        CPA16(qsm + r*144 + c8*16, Q + headoff + (size_t)(q0 + r) * DD + c8*8);
    }
    issue_kv(0, 0);
    CP_COMMIT();
    const int ntiles = qi + 1;
    if (ntiles > 1) issue_kv(1, 1);
    CP_COMMIT();

    if (tid < 64) { m_s[tid] = -1e30f; l_s[tid] = 0.f; }

    float acc[4][4] = {};

    for (int kt = 0; kt < ntiles; kt++) {
        const int kv0 = kt * 64;
        const uint32_t kb = ksm0 + (kt & 1) * KVH*2;
        const uint32_t vb = vsm0 + (kt & 1) * KVH*2;
        CP_WAIT(1);
        __syncthreads();

        // S = Q @ K^T
        float sfrag[4][4] = {};
        #pragma unroll
        for (int kk = 0; kk < HD; kk += 16) {
            uint32_t af[4];
            LDSM4(af[0], af[1], af[2], af[3],
                  qsm + (uint32_t)((wr + lrow) * HLD + kk + lko) * 2);
            #pragma unroll
            for (int n2 = 0; n2 < 2; n2++) {
                uint32_t r0, r1, r2, r3;
                LDSM4(r0, r1, r2, r3,
                      kb + (uint32_t)((wc + n2*16 + lrow) * HLD + kk + lko) * 2);
                mma16(sfrag[n2*2],   af, r0, r2);
                mma16(sfrag[n2*2+1], af, r1, r3);
            }
        }
        const bool diag = (kt == ntiles - 1);
        #pragma unroll
        for (int ni = 0; ni < 4; ni++) {
            int r0r = wr + g, r1 = r0r + 8;
            int cc = wc + (ni >> 1) * 16 + (ni & 1) * 8 + t * 2;
            float v0 = sfrag[ni][0]*0.125f, v1 = sfrag[ni][1]*0.125f;
            float v2 = sfrag[ni][2]*0.125f, v3 = sfrag[ni][3]*0.125f;
            if (diag) {
                int gr0 = q0 + r0r, gr1 = q0 + r1, gc = kv0 + cc;
                if (gc     > gr0) v0 = -1e30f;
                if (gc + 1 > gr0) v1 = -1e30f;
                if (gc     > gr1) v2 = -1e30f;
                if (gc + 1 > gr1) v3 = -1e30f;
            }
            *(float2*)&Ss[r0r*SLD + cc] = make_float2(v0, v1);
            *(float2*)&Ss[r1*SLD + cc]  = make_float2(v2, v3);
        }
        __syncthreads();

        // online softmax: 4 threads per row; writes P as fp16
        {
            int r = tid >> 2, c4o = tid & 3;
            float mold = m_s[r];
            float mx = mold;
            #pragma unroll
            for (int c4 = 0; c4 < 16; c4++) mx = fmaxf(mx, Ss[r*SLD + c4*4 + c4o]);
            mx = fmaxf(mx, __shfl_xor_sync(0xffffffffu, mx, 1));
            mx = fmaxf(mx, __shfl_xor_sync(0xffffffffu, mx, 2));
            float sum = 0.f;
            #pragma unroll
            for (int c4 = 0; c4 < 16; c4++) {
                float p = __expf(Ss[r*SLD + c4*4 + c4o] - mx);
                sum += p;
                Ps[r*HLD + c4*4 + c4o] = __float2half_rn(p);
            }
            sum += __shfl_xor_sync(0xffffffffu, sum, 1);
            sum += __shfl_xor_sync(0xffffffffu, sum, 2);
            if (c4o == 0) {
                float alpha = __expf(mold - mx);
                l_s[r] = l_s[r] * alpha + sum;
                m_s[r] = mx;
                a_s[r] = alpha;
            }
        }
        __syncthreads();

        // O = O*alpha + P @ V
        {
            float al0 = a_s[wr + g], al1 = a_s[wr + g + 8];
            #pragma unroll
            for (int ni = 0; ni < 4; ni++) {
                acc[ni][0] *= al0; acc[ni][1] *= al0;
                acc[ni][2] *= al1; acc[ni][3] *= al1;
            }
        }
        #pragma unroll
        for (int kk = 0; kk < 64; kk += 16) {
            uint32_t af[4];
            LDSM4(af[0], af[1], af[2], af[3],
                  psm + (uint32_t)((wr + lrow) * HLD + kk + lko) * 2);
            #pragma unroll
            for (int n2 = 0; n2 < 2; n2++) {
                uint32_t r0, r1, r2, r3;
                LDSM4T(r0, r1, r2, r3,
                       vb + (uint32_t)((kk + lrow) * HLD + wc + n2*16 + lko) * 2);
                mma16(acc[n2*2],   af, r0, r1);
                mma16(acc[n2*2+1], af, r2, r3);
            }
        }
        __syncthreads();
        if (kt + 2 < ntiles) issue_kv(kt + 2, kt & 1);
        CP_COMMIT();
    }

    // epilogue (fp16 out)
    {
        int r0r = wr + g, r1 = r0r + 8;
        float inv0 = 1.f / l_s[r0r], inv1 = 1.f / l_s[r1];
        #pragma unroll
        for (int ni = 0; ni < 4; ni++) {
            int cc = wc + (ni >> 1) * 16 + (ni & 1) * 8 + t * 2;
            *(__half2*)&O[headoff + (size_t)(q0 + r0r)*DD + cc] =
                __floats2half2_rn(acc[ni][0]*inv0, acc[ni][1]*inv0);
            *(__half2*)&O[headoff + (size_t)(q0 + r1)*DD + cc] =
                __floats2half2_rn(acc[ni][2]*inv1, acc[ni][3]*inv1);
        }
    }
}

// ---------------------------------------------------------------------------
extern "C" void kernel_launch(void* const* d_in, const int* in_sizes, int n_in,
                              void* d_out, int out_size)
{
    const float* x     = (const float*)d_in[0];
    const float* freqs = (const float*)d_in[1];
    // d_in[2] = attention_mask (pure causal; handled structurally)
    const float* Wq = (const float*)d_in[3];
    const float* Wk = (const float*)d_in[4];
    const float* Wv = (const float*)d_in[5];
    const float* Wo = (const float*)d_in[6];
    float* out = (float*)d_out;

    __half *pxh, *pQh, *pKh, *pVh, *pAh, *pWh;
    cudaGetSymbolAddress((void**)&pxh, g_xh);
    cudaGetSymbolAddress((void**)&pQh, g_Qh);
    cudaGetSymbolAddress((void**)&pKh, g_Kh);
    cudaGetSymbolAddress((void**)&pVh, g_Vh);
    cudaGetSymbolAddress((void**)&pAh, g_Ah);
    cudaGetSymbolAddress((void**)&pWh, g_Wh);

    // fused f32 -> f16 conversions (x + 4 weights)
    cvt_all<<<(2*ML*DD/4)/256, 256>>>(x, Wq, Wk, Wv, Wo, pxh, pWh);

    cudaFuncSetAttribute(gemm_f16p<0>, cudaFuncAttributeMaxDynamicSharedMemorySize, GEMM_SMEM);
    cudaFuncSetAttribute(gemm_f16p<1>, cudaFuncAttributeMaxDynamicSharedMemorySize, GEMM_SMEM);

    // Fused QKV projections with RoPE in epilogue (z0->Qh, z1->Kh, z2->Vh)
    gemm_f16p<0><<<dim3(DD/BN, ML/BM, 3), 256, GEMM_SMEM>>>(
        pxh, pWh, pWh + DD*DD, pWh + 2*DD*DD, pQh, pKh, pVh, nullptr, freqs);

    cudaFuncSetAttribute(flash_f16, cudaFuncAttributeMaxDynamicSharedMemorySize, FL_SMEM_BYTES);
    flash_f16<<<dim3(LL/64, BB*NH), 256, FL_SMEM_BYTES>>>(pQh, pKh, pVh, pAh);

    // Output projection: f16 A @ Wo^T -> f32 out
    gemm_f16p<1><<<dim3(DD/BN, ML/BM, 1), 256, GEMM_SMEM>>>(
        pAh, pWh + 3*DD*DD, nullptr, nullptr, nullptr, nullptr, nullptr, out, nullptr);
}

// round 9
// speedup vs baseline: 1.4604x; 1.2350x over previous
#include <cuda_runtime.h>
#include <cuda_fp16.h>
#include <cstdint>

// Problem constants: B=2, L=2048, D=1024, H=16, hd=64
#define BB 2
#define LL 2048
#define DD 1024
#define NH 16
#define HD 64
#define ML (BB*LL)          // 4096 rows

// fp16 scratch
static __device__ __half g_xh[ML*DD];
static __device__ __half g_Qh[ML*DD];
static __device__ __half g_Kh[ML*DD];
static __device__ __half g_Vh[ML*DD];
static __device__ __half g_Ah[ML*DD];
static __device__ __half g_Wh[4*DD*DD];

// ---------------------------------------------------------------------------
// helpers
// ---------------------------------------------------------------------------
__device__ __forceinline__ uint32_t smem_u32(const void* p) {
    uint32_t a;
    asm("{ .reg .u64 t; cvta.to.shared.u64 t, %1; cvt.u32.u64 %0, t; }" : "=r"(a) : "l"(p));
    return a;
}

__device__ __forceinline__ uint32_t f2h2(float x, float y) {
    __half2 h = __floats2half2_rn(x, y);
    return *(uint32_t*)&h;
}

#define CPA16(dst, src) \
    asm volatile("cp.async.cg.shared.global [%0], [%1], 16;" :: "r"(dst), "l"(src))
#define CP_COMMIT() asm volatile("cp.async.commit_group;" ::: "memory")
#define CP_WAIT(n)  asm volatile("cp.async.wait_group %0;" :: "n"(n) : "memory")

#define LDSM4(r0,r1,r2,r3, addr) \
    asm volatile("ldmatrix.sync.aligned.m8n8.x4.shared.b16 {%0,%1,%2,%3}, [%4];" \
        : "=r"(r0),"=r"(r1),"=r"(r2),"=r"(r3) : "r"(addr))

#define LDSM4T(r0,r1,r2,r3, addr) \
    asm volatile("ldmatrix.sync.aligned.m8n8.x4.trans.shared.b16 {%0,%1,%2,%3}, [%4];" \
        : "=r"(r0),"=r"(r1),"=r"(r2),"=r"(r3) : "r"(addr))

__device__ __forceinline__ void mma16(float* c, const uint32_t* a, uint32_t b0, uint32_t b1) {
    asm volatile("mma.sync.aligned.m16n8k16.row.col.f32.f16.f16.f32 "
        "{%0,%1,%2,%3}, {%4,%5,%6,%7}, {%8,%9}, {%0,%1,%2,%3};"
        : "+f"(c[0]), "+f"(c[1]), "+f"(c[2]), "+f"(c[3])
        : "r"(a[0]), "r"(a[1]), "r"(a[2]), "r"(a[3]), "r"(b0), "r"(b1));
}

// ---------------------------------------------------------------------------
// Fused f32 -> f16 conversion of x (4M elems) + 4 weights (1M each).
// ---------------------------------------------------------------------------
__global__ void cvt_all(const float* __restrict__ x,
                        const float* __restrict__ Wq, const float* __restrict__ Wk,
                        const float* __restrict__ Wv, const float* __restrict__ Wo,
                        __half* __restrict__ xh, __half* __restrict__ Wh)
{
    int i = blockIdx.x * blockDim.x + threadIdx.x;     // float4 index, 0..2M-1
    int chunk = i >> 18;
    const float* in;
    __half* out;
    size_t base;
    if (chunk < 4) { in = x; out = xh; base = (size_t)i * 4; }
    else {
        int w = chunk - 4;
        in = (w == 0) ? Wq : (w == 1) ? Wk : (w == 2) ? Wv : Wo;
        out = Wh + (size_t)w * DD * DD;
        base = (size_t)(i & 0x3FFFF) * 4;
    }
    float4 v = *(const float4*)&in[base];
    __half2 h0 = __floats2half2_rn(v.x, v.y);
    __half2 h1 = __floats2half2_rn(v.z, v.w);
    *(uint2*)&out[base] = make_uint2(*(uint32_t*)&h0, *(uint32_t*)&h1);
}

// ---------------------------------------------------------------------------
// Pipelined FP16 GEMM: C[M,N] = A[M,K] @ W[N,K]^T, 128x128x32 tiles, 8 warps,
// cp.async 3-stage.  MODE 0: fused QKV, RoPE applied in epilogue for z<2,
// all outputs fp16.  MODE 1: f32 out (final projection).
// ---------------------------------------------------------------------------
#define BM 128
#define BN 128
#define BK 32
#define ALD 40
#define STAGE_B 20480
#define GEMM_SMEM (3*STAGE_B)

template<int MODE>
__global__ __launch_bounds__(256) void gemm_f16p(
    const __half* __restrict__ A,
    const __half* __restrict__ Wa, const __half* __restrict__ Wb, const __half* __restrict__ Wc,
    __half* __restrict__ Qh, __half* __restrict__ Kh, __half* __restrict__ Vh,
    float* __restrict__ Cfin, const float* __restrict__ freqs)
{
    const int z = blockIdx.z;
    const __half* W = (z == 0) ? Wa : (z == 1) ? Wb : Wc;

    extern __shared__ char smem[];
    const uint32_t s0 = smem_u32(smem);

    const int tid  = threadIdx.x;
    const int lane = tid & 31, warp = tid >> 5;
    const int g = lane >> 2, t = lane & 3;
    const int lrow = lane & 15, lko = (lane >> 4) * 8;
    const int wm = (warp & 3) * 32;
    const int wn = (warp >> 2) * 64;
    const int row0 = blockIdx.y * BM, col0 = blockIdx.x * BN;

    auto load_stage = [&](int st, int k0) {
        uint32_t base = s0 + st * STAGE_B;
        #pragma unroll
        for (int i = 0; i < 2; i++) {
            int cid = tid + i * 256;
            int r = cid >> 2, c4 = cid & 3;
            CPA16(base + r*80 + c4*16,         A + (size_t)(row0 + r) * DD + k0 + c4*8);
            CPA16(base + 10240 + r*80 + c4*16, W + (size_t)(col0 + r) * DD + k0 + c4*8);
        }
        CP_COMMIT();
    };

    float c[2][8][4] = {};

    load_stage(0, 0);
    load_stage(1, BK);

    for (int ch = 0; ch < DD/BK; ch++) {
        CP_WAIT(1);
        __syncthreads();
        if (ch + 2 < DD/BK) load_stage((ch + 2) % 3, (ch + 2) * BK);
        else CP_COMMIT();

        const uint32_t ab = s0 + (ch % 3) * STAGE_B;
        const uint32_t bb = ab + 10240;

        #pragma unroll
        for (int ks = 0; ks < 2; ks++) {
            const int kk = ks * 16;
            uint32_t af[2][4];
            #pragma unroll
            for (int mi = 0; mi < 2; mi++) {
                uint32_t ad = ab + (uint32_t)((wm + mi*16 + lrow) * ALD + kk + lko) * 2;
                LDSM4(af[mi][0], af[mi][1], af[mi][2], af[mi][3], ad);
            }
            #pragma unroll
            for (int n2 = 0; n2 < 4; n2++) {
                uint32_t r0, r1, r2, r3;
                uint32_t bd = bb + (uint32_t)((wn + n2*16 + lrow) * ALD + kk + lko) * 2;
                LDSM4(r0, r1, r2, r3, bd);
                #pragma unroll
                for (int mi = 0; mi < 2; mi++) {
                    mma16(c[mi][n2*2],   af[mi], r0, r2);
                    mma16(c[mi][n2*2+1], af[mi], r1, r3);
                }
            }
        }
        __syncthreads();
    }

    #pragma unroll
    for (int mi = 0; mi < 2; mi++) {
        int r = row0 + wm + mi * 16 + g;
        #pragma unroll
        for (int ni = 0; ni < 8; ni++) {
            int cc = col0 + wn + (ni >> 1) * 16 + (ni & 1) * 8 + t * 2;
            float v0 = c[mi][ni][0], v1 = c[mi][ni][1];
            float v2 = c[mi][ni][2], v3 = c[mi][ni][3];
            if (MODE == 1) {
                *(float2*)&Cfin[(size_t)r * DD + cc]       = make_float2(v0, v1);
                *(float2*)&Cfin[(size_t)(r + 8) * DD + cc] = make_float2(v2, v3);
            } else if (z == 2) {
                *(__half2*)&Vh[(size_t)r * DD + cc]       = __floats2half2_rn(v0, v1);
                *(__half2*)&Vh[(size_t)(r + 8) * DD + cc] = __floats2half2_rn(v2, v3);
            } else {
                // fused RoPE: (v0,v1) is an adjacent (even,odd) pair within a head
                __half* C = z ? Kh : Qh;
                int pp = (cc & (HD - 1)) >> 1;
                int l0 = r & (LL - 1), l1 = (r + 8) & (LL - 1);
                float2 f0 = *(const float2*)&freqs[(l0 * (HD/2) + pp) * 2];
                float2 f1 = *(const float2*)&freqs[(l1 * (HD/2) + pp) * 2];
                *(__half2*)&C[(size_t)r * DD + cc] =
                    __floats2half2_rn(v0*f0.x - v1*f0.y, v0*f0.y + v1*f0.x);
                *(__half2*)&C[(size_t)(r + 8) * DD + cc] =
                    __floats2half2_rn(v2*f1.x - v3*f1.y, v2*f1.y + v3*f1.x);
            }
        }
    }
}

// ---------------------------------------------------------------------------
// Flash attention (causal), FA2-style register-resident softmax.
// BQ=128, kv-tile 64. 8 warps; warp w owns q-rows w*16..w*16+15, ALL 64 kv.
// S C-fragments reinterpreted as P A-fragments (no smem round trip).
// smem: Q[128][72] + K/V double buffers [64][72] -> 54 KB, 2 syncs/tile.
// ---------------------------------------------------------------------------
#define BQ 128
#define HLD 72
#define QB  (BQ*HLD*2)           // Q tile bytes
#define KVB (64*HLD*2)           // one K or V buffer bytes
#define FL_SMEM_BYTES (QB + 4*KVB)

__global__ __launch_bounds__(256) void flash_f16(
    const __half* __restrict__ Q, const __half* __restrict__ K,
    const __half* __restrict__ V, __half* __restrict__ O)
{
    extern __shared__ __half hsm[];
    const uint32_t qsm  = smem_u32(hsm);
    const uint32_t ksm0 = qsm + QB;           // K0, K1, V0, V1
    const uint32_t vsm0 = qsm + QB + 2*KVB;

    const int tid = threadIdx.x;
    const int lane = tid & 31, warp = tid >> 5;
    const int g = lane >> 2, t = lane & 3;
    const int lrow = lane & 15, lko = (lane >> 4) * 8;
    const int wr = warp * 16;                 // this warp's q-row block
    const int b = blockIdx.y >> 4, h = blockIdx.y & 15;
    const int qi = (int)gridDim.x - 1 - (int)blockIdx.x;   // heavy blocks first
    const int q0 = qi * BQ;
    const size_t headoff = (size_t)b * LL * DD + (size_t)h * HD;

    auto issue_kv = [&](int kt, int buf) {
        const int kv0 = kt * 64;
        uint32_t kb = ksm0 + buf * KVB;
        uint32_t vb = vsm0 + buf * KVB;
        #pragma unroll
        for (int i = 0; i < 4; i++) {
            int cid = tid + i * 256;          // 0..1023
            int isv = cid >> 9;
            int cc  = cid & 511;
            int r = cc >> 3, c8 = cc & 7;
            const __half* src = (isv ? V : K) + headoff + (size_t)(kv0 + r) * DD + c8*8;
            CPA16((isv ? vb : kb) + r*144 + c8*16, src);
        }
    };

    // group 0: Q tile (128 rows) + kv tile 0;  group 1: kv tile 1
    #pragma unroll
    for (int i = 0; i < 4; i++) {
        int cid = tid + i * 256;              // 0..1023
        int r = cid >> 3, c8 = cid & 7;
        CPA16(qsm + r*144 + c8*16, Q + headoff + (size_t)(q0 + r) * DD + c8*8);
    }
    issue_kv(0, 0);
    CP_COMMIT();
    const int ntiles = 2 * qi + 2;
    issue_kv(1, 1);
    CP_COMMIT();

    uint32_t qf[4][4];
    float acc[8][4] = {};
    float m0 = -1e30f, m1 = -1e30f, l0 = 0.f, l1 = 0.f;

    for (int kt = 0; kt < ntiles; kt++) {
        const int kv0 = kt * 64;
        const uint32_t kb = ksm0 + (kt & 1) * KVB;
        const uint32_t vb = vsm0 + (kt & 1) * KVB;
        CP_WAIT(1);
        __syncthreads();

        if (kt == 0) {
            #pragma unroll
            for (int ks = 0; ks < 4; ks++)
                LDSM4(qf[ks][0], qf[ks][1], qf[ks][2], qf[ks][3],
                      qsm + (uint32_t)((wr + lrow) * HLD + ks*16 + lko) * 2);
        }

        // skip warps whose 16 rows are entirely masked (last tile, rows < 64)
        if (!(kt == ntiles - 1 && wr < 64)) {
            // S = Q @ K^T : warp computes 16 x 64
            float sf[8][4] = {};
            #pragma unroll
            for (int ks = 0; ks < 4; ks++) {
                #pragma unroll
                for (int ng = 0; ng < 4; ng++) {
                    uint32_t r0, r1, r2, r3;
                    LDSM4(r0, r1, r2, r3,
                          kb + (uint32_t)((ng*16 + lrow) * HLD + ks*16 + lko) * 2);
                    mma16(sf[ng*2],   qf[ks], r0, r2);
                    mma16(sf[ng*2+1], qf[ks], r1, r3);
                }
            }
            // scale + causal mask (only the 2 diagonal tiles need it)
            const int gr0 = q0 + wr + g, gr1 = gr0 + 8;
            if (kt >= ntiles - 2) {
                #pragma unroll
                for (int nb = 0; nb < 8; nb++) {
                    int gc = kv0 + nb*8 + t*2;
                    sf[nb][0] = (gc     > gr0) ? -1e30f : sf[nb][0]*0.125f;
                    sf[nb][1] = (gc + 1 > gr0) ? -1e30f : sf[nb][1]*0.125f;
                    sf[nb][2] = (gc     > gr1) ? -1e30f : sf[nb][2]*0.125f;
                    sf[nb][3] = (gc + 1 > gr1) ? -1e30f : sf[nb][3]*0.125f;
                }
            } else {
                #pragma unroll
                for (int nb = 0; nb < 8; nb++) {
                    sf[nb][0] *= 0.125f; sf[nb][1] *= 0.125f;
                    sf[nb][2] *= 0.125f; sf[nb][3] *= 0.125f;
                }
            }
            // register-resident online softmax (rows g and g+8)
            float rmx0 = -1e30f, rmx1 = -1e30f;
            #pragma unroll
            for (int nb = 0; nb < 8; nb++) {
                rmx0 = fmaxf(rmx0, fmaxf(sf[nb][0], sf[nb][1]));
                rmx1 = fmaxf(rmx1, fmaxf(sf[nb][2], sf[nb][3]));
            }
            rmx0 = fmaxf(rmx0, __shfl_xor_sync(0xffffffffu, rmx0, 1));
            rmx0 = fmaxf(rmx0, __shfl_xor_sync(0xffffffffu, rmx0, 2));
            rmx1 = fmaxf(rmx1, __shfl_xor_sync(0xffffffffu, rmx1, 1));
            rmx1 = fmaxf(rmx1, __shfl_xor_sync(0xffffffffu, rmx1, 2));
            float nm0 = fmaxf(m0, rmx0), nm1 = fmaxf(m1, rmx1);
            float al0 = __expf(m0 - nm0), al1 = __expf(m1 - nm1);
            m0 = nm0; m1 = nm1;
            float s0 = 0.f, s1 = 0.f;
            #pragma unroll
            for (int nb = 0; nb < 8; nb++) {
                sf[nb][0] = __expf(sf[nb][0] - nm0); s0 += sf[nb][0];
                sf[nb][1] = __expf(sf[nb][1] - nm0); s0 += sf[nb][1];
                sf[nb][2] = __expf(sf[nb][2] - nm1); s1 += sf[nb][2];
                sf[nb][3] = __expf(sf[nb][3] - nm1); s1 += sf[nb][3];
            }
            s0 += __shfl_xor_sync(0xffffffffu, s0, 1);
            s0 += __shfl_xor_sync(0xffffffffu, s0, 2);
            s1 += __shfl_xor_sync(0xffffffffu, s1, 1);
            s1 += __shfl_xor_sync(0xffffffffu, s1, 2);
            l0 = l0 * al0 + s0;
            l1 = l1 * al1 + s1;
            #pragma unroll
            for (int nb = 0; nb < 8; nb++) {
                acc[nb][0] *= al0; acc[nb][1] *= al0;
                acc[nb][2] *= al1; acc[nb][3] *= al1;
            }
            // O += P @ V  (P packed from S fragments, no smem)
            #pragma unroll
            for (int ks = 0; ks < 4; ks++) {
                uint32_t pf[4];
                pf[0] = f2h2(sf[2*ks][0],   sf[2*ks][1]);
                pf[1] = f2h2(sf[2*ks][2],   sf[2*ks][3]);
                pf[2] = f2h2(sf[2*ks+1][0], sf[2*ks+1][1]);
                pf[3] = f2h2(sf[2*ks+1][2], sf[2*ks+1][3]);
                #pragma unroll
                for (int ng = 0; ng < 4; ng++) {
                    uint32_t r0, r1, r2, r3;   // trans: rows = kv, cols = hd
                    LDSM4T(r0, r1, r2, r3,
                           vb + (uint32_t)((ks*16 + lrow) * HLD + ng*16 + lko) * 2);
                    mma16(acc[ng*2],   pf, r0, r1);
                    mma16(acc[ng*2+1], pf, r2, r3);
                }
            }
        }

        __syncthreads();
        if (kt + 2 < ntiles) issue_kv(kt + 2, kt & 1);
        CP_COMMIT();
    }

    // epilogue (fp16 out)
    {
        int r0r = q0 + wr + g, r1 = r0r + 8;
        float inv0 = 1.f / l0, inv1 = 1.f / l1;
        #pragma unroll
        for (int nb = 0; nb < 8; nb++) {
            int cc = nb*8 + t*2;
            *(__half2*)&O[headoff + (size_t)r0r*DD + cc] =
                __floats2half2_rn(acc[nb][0]*inv0, acc[nb][1]*inv0);
            *(__half2*)&O[headoff + (size_t)r1*DD + cc] =
                __floats2half2_rn(acc[nb][2]*inv1, acc[nb][3]*inv1);
        }
    }
}

// ---------------------------------------------------------------------------
extern "C" void kernel_launch(void* const* d_in, const int* in_sizes, int n_in,
                              void* d_out, int out_size)
{
    const float* x     = (const float*)d_in[0];
    const float* freqs = (const float*)d_in[1];
    // d_in[2] = attention_mask (pure causal; handled structurally)
    const float* Wq = (const float*)d_in[3];
    const float* Wk = (const float*)d_in[4];
    const float* Wv = (const float*)d_in[5];
    const float* Wo = (const float*)d_in[6];
    float* out = (float*)d_out;

    __half *pxh, *pQh, *pKh, *pVh, *pAh, *pWh;
    cudaGetSymbolAddress((void**)&pxh, g_xh);
    cudaGetSymbolAddress((void**)&pQh, g_Qh);
    cudaGetSymbolAddress((void**)&pKh, g_Kh);
    cudaGetSymbolAddress((void**)&pVh, g_Vh);
    cudaGetSymbolAddress((void**)&pAh, g_Ah);
    cudaGetSymbolAddress((void**)&pWh, g_Wh);

    // fused f32 -> f16 conversions (x + 4 weights)
    cvt_all<<<(2*ML*DD/4)/256, 256>>>(x, Wq, Wk, Wv, Wo, pxh, pWh);

    cudaFuncSetAttribute(gemm_f16p<0>, cudaFuncAttributeMaxDynamicSharedMemorySize, GEMM_SMEM);
    cudaFuncSetAttribute(gemm_f16p<1>, cudaFuncAttributeMaxDynamicSharedMemorySize, GEMM_SMEM);

    // Fused QKV projections with RoPE in epilogue (z0->Qh, z1->Kh, z2->Vh)
    gemm_f16p<0><<<dim3(DD/BN, ML/BM, 3), 256, GEMM_SMEM>>>(
        pxh, pWh, pWh + DD*DD, pWh + 2*DD*DD, pQh, pKh, pVh, nullptr, freqs);

    cudaFuncSetAttribute(flash_f16, cudaFuncAttributeMaxDynamicSharedMemorySize, FL_SMEM_BYTES);
    flash_f16<<<dim3(LL/BQ, BB*NH), 256, FL_SMEM_BYTES>>>(pQh, pKh, pVh, pAh);

    // Output projection: f16 A @ Wo^T -> f32 out
    gemm_f16p<1><<<dim3(DD/BN, ML/BM, 1), 256, GEMM_SMEM>>>(
        pAh, pWh + 3*DD*DD, nullptr, nullptr, nullptr, nullptr, nullptr, out, nullptr);
}

// round 10
// speedup vs baseline: 1.5457x; 1.0584x over previous
#include <cuda_runtime.h>
#include <cuda_fp16.h>
#include <cstdint>

// Problem constants: B=2, L=2048, D=1024, H=16, hd=64
#define BB 2
#define LL 2048
#define DD 1024
#define NH 16
#define HD 64
#define ML (BB*LL)          // 4096 rows

// fp16 scratch
static __device__ __half g_xh[ML*DD];
static __device__ __half g_Qh[ML*DD];
static __device__ __half g_Kh[ML*DD];
static __device__ __half g_Vh[ML*DD];
static __device__ __half g_Ah[ML*DD];
static __device__ __half g_Wh[4*DD*DD];

// ---------------------------------------------------------------------------
// helpers
// ---------------------------------------------------------------------------
__device__ __forceinline__ uint32_t smem_u32(const void* p) {
    uint32_t a;
    asm("{ .reg .u64 t; cvta.to.shared.u64 t, %1; cvt.u32.u64 %0, t; }" : "=r"(a) : "l"(p));
    return a;
}

__device__ __forceinline__ uint32_t f2h2(float x, float y) {
    __half2 h = __floats2half2_rn(x, y);
    return *(uint32_t*)&h;
}

#define CPA16(dst, src) \
    asm volatile("cp.async.cg.shared.global [%0], [%1], 16;" :: "r"(dst), "l"(src))
#define CP_COMMIT() asm volatile("cp.async.commit_group;" ::: "memory")
#define CP_WAIT(n)  asm volatile("cp.async.wait_group %0;" :: "n"(n) : "memory")

#define LDSM4(r0,r1,r2,r3, addr) \
    asm volatile("ldmatrix.sync.aligned.m8n8.x4.shared.b16 {%0,%1,%2,%3}, [%4];" \
        : "=r"(r0),"=r"(r1),"=r"(r2),"=r"(r3) : "r"(addr))

#define LDSM4T(r0,r1,r2,r3, addr) \
    asm volatile("ldmatrix.sync.aligned.m8n8.x4.trans.shared.b16 {%0,%1,%2,%3}, [%4];" \
        : "=r"(r0),"=r"(r1),"=r"(r2),"=r"(r3) : "r"(addr))

__device__ __forceinline__ void mma16(float* c, const uint32_t* a, uint32_t b0, uint32_t b1) {
    asm volatile("mma.sync.aligned.m16n8k16.row.col.f32.f16.f16.f32 "
        "{%0,%1,%2,%3}, {%4,%5,%6,%7}, {%8,%9}, {%0,%1,%2,%3};"
        : "+f"(c[0]), "+f"(c[1]), "+f"(c[2]), "+f"(c[3])
        : "r"(a[0]), "r"(a[1]), "r"(a[2]), "r"(a[3]), "r"(b0), "r"(b1));
}

// ---------------------------------------------------------------------------
// Fused f32 -> f16 conversion of x (4M elems) + 4 weights (1M each).
// ---------------------------------------------------------------------------
__global__ void cvt_all(const float* __restrict__ x,
                        const float* __restrict__ Wq, const float* __restrict__ Wk,
                        const float* __restrict__ Wv, const float* __restrict__ Wo,
                        __half* __restrict__ xh, __half* __restrict__ Wh)
{
    int i = blockIdx.x * blockDim.x + threadIdx.x;     // float4 index, 0..2M-1
    int chunk = i >> 18;
    const float* in;
    __half* out;
    size_t base;
    if (chunk < 4) { in = x; out = xh; base = (size_t)i * 4; }
    else {
        int w = chunk - 4;
        in = (w == 0) ? Wq : (w == 1) ? Wk : (w == 2) ? Wv : Wo;
        out = Wh + (size_t)w * DD * DD;
        base = (size_t)(i & 0x3FFFF) * 4;
    }
    float4 v = *(const float4*)&in[base];
    __half2 h0 = __floats2half2_rn(v.x, v.y);
    __half2 h1 = __floats2half2_rn(v.z, v.w);
    *(uint2*)&out[base] = make_uint2(*(uint32_t*)&h0, *(uint32_t*)&h1);
}

// ---------------------------------------------------------------------------
// Pipelined FP16 GEMM: C[M,N] = A[M,K] @ W[N,K]^T, 128x128x64 tiles, 8 warps,
// cp.async 2-stage (stage = 36 KB), 4 k-steps of uninterrupted MMA per
// barrier window.  MODE 0: fused QKV, RoPE in epilogue for z<2, fp16 out.
// MODE 1: f32 out (final projection).  Smem row stride 72 halves (144B).
// ---------------------------------------------------------------------------
#define BM 128
#define BN 128
#define BK 64
#define ALD 72
#define ATILE_B (BM*ALD*2)          // 18432 bytes
#define STAGE_B (2*ATILE_B)         // A + B = 36864 bytes
#define GEMM_SMEM (2*STAGE_B)       // 73728 bytes

template<int MODE>
__global__ __launch_bounds__(256) void gemm_f16p(
    const __half* __restrict__ A,
    const __half* __restrict__ Wa, const __half* __restrict__ Wb, const __half* __restrict__ Wc,
    __half* __restrict__ Qh, __half* __restrict__ Kh, __half* __restrict__ Vh,
    float* __restrict__ Cfin, const float* __restrict__ freqs)
{
    const int z = blockIdx.z;
    const __half* W = (z == 0) ? Wa : (z == 1) ? Wb : Wc;

    extern __shared__ char smem[];
    const uint32_t s0 = smem_u32(smem);

    const int tid  = threadIdx.x;
    const int lane = tid & 31, warp = tid >> 5;
    const int g = lane >> 2, t = lane & 3;
    const int lrow = lane & 15, lko = (lane >> 4) * 8;
    const int wm = (warp & 3) * 32;
    const int wn = (warp >> 2) * 64;
    const int row0 = blockIdx.y * BM, col0 = blockIdx.x * BN;

    // 2048 16B-chunks per stage (1024 A + 1024 B); 8 per thread
    auto load_stage = [&](int st, int k0) {
        uint32_t base = s0 + st * STAGE_B;
        #pragma unroll
        for (int i = 0; i < 4; i++) {
            int cid = tid + i * 256;          // 0..1023
            int r = cid >> 3, c8 = cid & 7;
            CPA16(base + r*144 + c8*16,           A + (size_t)(row0 + r) * DD + k0 + c8*8);
            CPA16(base + ATILE_B + r*144 + c8*16, W + (size_t)(col0 + r) * DD + k0 + c8*8);
        }
        CP_COMMIT();
    };

    float c[2][8][4] = {};

    load_stage(0, 0);
    load_stage(1, BK);

    for (int ch = 0; ch < DD/BK; ch++) {
        CP_WAIT(1);
        __syncthreads();

        const uint32_t ab = s0 + (ch & 1) * STAGE_B;
        const uint32_t bb = ab + ATILE_B;

        #pragma unroll
        for (int ks = 0; ks < 4; ks++) {
            const int kk = ks * 16;
            uint32_t af[2][4];
            #pragma unroll
            for (int mi = 0; mi < 2; mi++) {
                uint32_t ad = ab + (uint32_t)((wm + mi*16 + lrow) * ALD + kk + lko) * 2;
                LDSM4(af[mi][0], af[mi][1], af[mi][2], af[mi][3], ad);
            }
            #pragma unroll
            for (int n2 = 0; n2 < 4; n2++) {
                uint32_t r0, r1, r2, r3;
                uint32_t bd = bb + (uint32_t)((wn + n2*16 + lrow) * ALD + kk + lko) * 2;
                LDSM4(r0, r1, r2, r3, bd);
                #pragma unroll
                for (int mi = 0; mi < 2; mi++) {
                    mma16(c[mi][n2*2],   af[mi], r0, r2);
                    mma16(c[mi][n2*2+1], af[mi], r1, r3);
                }
            }
        }
        __syncthreads();
        if (ch + 2 < DD/BK) load_stage(ch & 1, (ch + 2) * BK);
        else CP_COMMIT();
    }

    #pragma unroll
    for (int mi = 0; mi < 2; mi++) {
        int r = row0 + wm + mi * 16 + g;
        #pragma unroll
        for (int ni = 0; ni < 8; ni++) {
            int cc = col0 + wn + (ni >> 1) * 16 + (ni & 1) * 8 + t * 2;
            float v0 = c[mi][ni][0], v1 = c[mi][ni][1];
            float v2 = c[mi][ni][2], v3 = c[mi][ni][3];
            if (MODE == 1) {
                *(float2*)&Cfin[(size_t)r * DD + cc]       = make_float2(v0, v1);
                *(float2*)&Cfin[(size_t)(r + 8) * DD + cc] = make_float2(v2, v3);
            } else if (z == 2) {
                *(__half2*)&Vh[(size_t)r * DD + cc]       = __floats2half2_rn(v0, v1);
                *(__half2*)&Vh[(size_t)(r + 8) * DD + cc] = __floats2half2_rn(v2, v3);
            } else {
                // fused RoPE: (v0,v1) is an adjacent (even,odd) pair within a head
                __half* C = z ? Kh : Qh;
                int pp = (cc & (HD - 1)) >> 1;
                int l0 = r & (LL - 1), l1 = (r + 8) & (LL - 1);
                float2 f0 = *(const float2*)&freqs[(l0 * (HD/2) + pp) * 2];
                float2 f1 = *(const float2*)&freqs[(l1 * (HD/2) + pp) * 2];
                *(__half2*)&C[(size_t)r * DD + cc] =
                    __floats2half2_rn(v0*f0.x - v1*f0.y, v0*f0.y + v1*f0.x);
                *(__half2*)&C[(size_t)(r + 8) * DD + cc] =
                    __floats2half2_rn(v2*f1.x - v3*f1.y, v2*f1.y + v3*f1.x);
            }
        }
    }
}

// ---------------------------------------------------------------------------
// Flash attention (causal), FA2-style register-resident softmax (R9 shape).
// BQ=128, kv-tile 64. 8 warps; warp w owns q-rows w*16..w*16+15, ALL 64 kv.
// ---------------------------------------------------------------------------
#define BQ 128
#define HLD 72
#define QB  (BQ*HLD*2)           // Q tile bytes
#define KVB (64*HLD*2)           // one K or V buffer bytes
#define FL_SMEM_BYTES (QB + 4*KVB)

__global__ __launch_bounds__(256) void flash_f16(
    const __half* __restrict__ Q, const __half* __restrict__ K,
    const __half* __restrict__ V, __half* __restrict__ O)
{
    extern __shared__ __half hsm[];
    const uint32_t qsm  = smem_u32(hsm);
    const uint32_t ksm0 = qsm + QB;           // K0, K1, V0, V1
    const uint32_t vsm0 = qsm + QB + 2*KVB;

    const int tid = threadIdx.x;
    const int lane = tid & 31, warp = tid >> 5;
    const int g = lane >> 2, t = lane & 3;
    const int lrow = lane & 15, lko = (lane >> 4) * 8;
    const int wr = warp * 16;                 // this warp's q-row block
    const int b = blockIdx.y >> 4, h = blockIdx.y & 15;
    const int qi = (int)gridDim.x - 1 - (int)blockIdx.x;   // heavy blocks first
    const int q0 = qi * BQ;
    const size_t headoff = (size_t)b * LL * DD + (size_t)h * HD;

    auto issue_kv = [&](int kt, int buf) {
        const int kv0 = kt * 64;
        uint32_t kb = ksm0 + buf * KVB;
        uint32_t vb = vsm0 + buf * KVB;
        #pragma unroll
        for (int i = 0; i < 4; i++) {
            int cid = tid + i * 256;          // 0..1023
            int isv = cid >> 9;
            int cc  = cid & 511;
            int r = cc >> 3, c8 = cc & 7;
            const __half* src = (isv ? V : K) + headoff + (size_t)(kv0 + r) * DD + c8*8;
            CPA16((isv ? vb : kb) + r*144 + c8*16, src);
        }
    };

    // group 0: Q tile (128 rows) + kv tile 0;  group 1: kv tile 1
    #pragma unroll
    for (int i = 0; i < 4; i++) {
        int cid = tid + i * 256;              // 0..1023
        int r = cid >> 3, c8 = cid & 7;
        CPA16(qsm + r*144 + c8*16, Q + headoff + (size_t)(q0 + r) * DD + c8*8);
    }
    issue_kv(0, 0);
    CP_COMMIT();
    const int ntiles = 2 * qi + 2;
    issue_kv(1, 1);
    CP_COMMIT();

    uint32_t qf[4][4];
    float acc[8][4] = {};
    float m0 = -1e30f, m1 = -1e30f, l0 = 0.f, l1 = 0.f;

    for (int kt = 0; kt < ntiles; kt++) {
        const int kv0 = kt * 64;
        const uint32_t kb = ksm0 + (kt & 1) * KVB;
        const uint32_t vb = vsm0 + (kt & 1) * KVB;
        CP_WAIT(1);
        __syncthreads();

        if (kt == 0) {
            #pragma unroll
            for (int ks = 0; ks < 4; ks++)
                LDSM4(qf[ks][0], qf[ks][1], qf[ks][2], qf[ks][3],
                      qsm + (uint32_t)((wr + lrow) * HLD + ks*16 + lko) * 2);
        }

        // skip warps whose 16 rows are entirely masked (last tile, rows < 64)
        if (!(kt == ntiles - 1 && wr < 64)) {
            // S = Q @ K^T : warp computes 16 x 64
            float sf[8][4] = {};
            #pragma unroll
            for (int ks = 0; ks < 4; ks++) {
                #pragma unroll
                for (int ng = 0; ng < 4; ng++) {
                    uint32_t r0, r1, r2, r3;
                    LDSM4(r0, r1, r2, r3,
                          kb + (uint32_t)((ng*16 + lrow) * HLD + ks*16 + lko) * 2);
                    mma16(sf[ng*2],   qf[ks], r0, r2);
                    mma16(sf[ng*2+1], qf[ks], r1, r3);
                }
            }
            // scale + causal mask (only the 2 diagonal tiles need it)
            const int gr0 = q0 + wr + g, gr1 = gr0 + 8;
            if (kt >= ntiles - 2) {
                #pragma unroll
                for (int nb = 0; nb < 8; nb++) {
                    int gc = kv0 + nb*8 + t*2;
                    sf[nb][0] = (gc     > gr0) ? -1e30f : sf[nb][0]*0.125f;
                    sf[nb][1] = (gc + 1 > gr0) ? -1e30f : sf[nb][1]*0.125f;
                    sf[nb][2] = (gc     > gr1) ? -1e30f : sf[nb][2]*0.125f;
                    sf[nb][3] = (gc + 1 > gr1) ? -1e30f : sf[nb][3]*0.125f;
                }
            } else {
                #pragma unroll
                for (int nb = 0; nb < 8; nb++) {
                    sf[nb][0] *= 0.125f; sf[nb][1] *= 0.125f;
                    sf[nb][2] *= 0.125f; sf[nb][3] *= 0.125f;
                }
            }
            // register-resident online softmax (rows g and g+8)
            float rmx0 = -1e30f, rmx1 = -1e30f;
            #pragma unroll
            for (int nb = 0; nb < 8; nb++) {
                rmx0 = fmaxf(rmx0, fmaxf(sf[nb][0], sf[nb][1]));
                rmx1 = fmaxf(rmx1, fmaxf(sf[nb][2], sf[nb][3]));
            }
            rmx0 = fmaxf(rmx0, __shfl_xor_sync(0xffffffffu, rmx0, 1));
            rmx0 = fmaxf(rmx0, __shfl_xor_sync(0xffffffffu, rmx0, 2));
            rmx1 = fmaxf(rmx1, __shfl_xor_sync(0xffffffffu, rmx1, 1));
            rmx1 = fmaxf(rmx1, __shfl_xor_sync(0xffffffffu, rmx1, 2));
            float nm0 = fmaxf(m0, rmx0), nm1 = fmaxf(m1, rmx1);
            float al0 = __expf(m0 - nm0), al1 = __expf(m1 - nm1);
            m0 = nm0; m1 = nm1;
            float s0 = 0.f, s1 = 0.f;
            #pragma unroll
            for (int nb = 0; nb < 8; nb++) {
                sf[nb][0] = __expf(sf[nb][0] - nm0); s0 += sf[nb][0];
                sf[nb][1] = __expf(sf[nb][1] - nm0); s0 += sf[nb][1];
                sf[nb][2] = __expf(sf[nb][2] - nm1); s1 += sf[nb][2];
                sf[nb][3] = __expf(sf[nb][3] - nm1); s1 += sf[nb][3];
            }
            s0 += __shfl_xor_sync(0xffffffffu, s0, 1);
            s0 += __shfl_xor_sync(0xffffffffu, s0, 2);
            s1 += __shfl_xor_sync(0xffffffffu, s1, 1);
            s1 += __shfl_xor_sync(0xffffffffu, s1, 2);
            l0 = l0 * al0 + s0;
            l1 = l1 * al1 + s1;
            #pragma unroll
            for (int nb = 0; nb < 8; nb++) {
                acc[nb][0] *= al0; acc[nb][1] *= al0;
                acc[nb][2] *= al1; acc[nb][3] *= al1;
            }
            // O += P @ V  (P packed from S fragments, no smem)
            #pragma unroll
            for (int ks = 0; ks < 4; ks++) {
                uint32_t pf[4];
                pf[0] = f2h2(sf[2*ks][0],   sf[2*ks][1]);
                pf[1] = f2h2(sf[2*ks][2],   sf[2*ks][3]);
                pf[2] = f2h2(sf[2*ks+1][0], sf[2*ks+1][1]);
                pf[3] = f2h2(sf[2*ks+1][2], sf[2*ks+1][3]);
                #pragma unroll
                for (int ng = 0; ng < 4; ng++) {
                    uint32_t r0, r1, r2, r3;   // trans: rows = kv, cols = hd
                    LDSM4T(r0, r1, r2, r3,
                           vb + (uint32_t)((ks*16 + lrow) * HLD + ng*16 + lko) * 2);
                    mma16(acc[ng*2],   pf, r0, r1);
                    mma16(acc[ng*2+1], pf, r2, r3);
                }
            }
        }

        __syncthreads();
        if (kt + 2 < ntiles) issue_kv(kt + 2, kt & 1);
        CP_COMMIT();
    }

    // epilogue (fp16 out)
    {
        int r0r = q0 + wr + g, r1 = r0r + 8;
        float inv0 = 1.f / l0, inv1 = 1.f / l1;
        #pragma unroll
        for (int nb = 0; nb < 8; nb++) {
            int cc = nb*8 + t*2;
            *(__half2*)&O[headoff + (size_t)r0r*DD + cc] =
                __floats2half2_rn(acc[nb][0]*inv0, acc[nb][1]*inv0);
            *(__half2*)&O[headoff + (size_t)r1*DD + cc] =
                __floats2half2_rn(acc[nb][2]*inv1, acc[nb][3]*inv1);
        }
    }
}

// ---------------------------------------------------------------------------
extern "C" void kernel_launch(void* const* d_in, const int* in_sizes, int n_in,
                              void* d_out, int out_size)
{
    const float* x     = (const float*)d_in[0];
    const float* freqs = (const float*)d_in[1];
    // d_in[2] = attention_mask (pure causal; handled structurally)
    const float* Wq = (const float*)d_in[3];
    const float* Wk = (const float*)d_in[4];
    const float* Wv = (const float*)d_in[5];
    const float* Wo = (const float*)d_in[6];
    float* out = (float*)d_out;

    __half *pxh, *pQh, *pKh, *pVh, *pAh, *pWh;
    cudaGetSymbolAddress((void**)&pxh, g_xh);
    cudaGetSymbolAddress((void**)&pQh, g_Qh);
    cudaGetSymbolAddress((void**)&pKh, g_Kh);
    cudaGetSymbolAddress((void**)&pVh, g_Vh);
    cudaGetSymbolAddress((void**)&pAh, g_Ah);
    cudaGetSymbolAddress((void**)&pWh, g_Wh);

    // fused f32 -> f16 conversions (x + 4 weights)
    cvt_all<<<(2*ML*DD/4)/256, 256>>>(x, Wq, Wk, Wv, Wo, pxh, pWh);

    cudaFuncSetAttribute(gemm_f16p<0>, cudaFuncAttributeMaxDynamicSharedMemorySize, GEMM_SMEM);
    cudaFuncSetAttribute(gemm_f16p<1>, cudaFuncAttributeMaxDynamicSharedMemorySize, GEMM_SMEM);

    // Fused QKV projections with RoPE in epilogue (z0->Qh, z1->Kh, z2->Vh)
    gemm_f16p<0><<<dim3(DD/BN, ML/BM, 3), 256, GEMM_SMEM>>>(
        pxh, pWh, pWh + DD*DD, pWh + 2*DD*DD, pQh, pKh, pVh, nullptr, freqs);

    cudaFuncSetAttribute(flash_f16, cudaFuncAttributeMaxDynamicSharedMemorySize, FL_SMEM_BYTES);
    flash_f16<<<dim3(LL/BQ, BB*NH), 256, FL_SMEM_BYTES>>>(pQh, pKh, pVh, pAh);

    // Output projection: f16 A @ Wo^T -> f32 out
    gemm_f16p<1><<<dim3(DD/BN, ML/BM, 1), 256, GEMM_SMEM>>>(
        pAh, pWh + 3*DD*DD, nullptr, nullptr, nullptr, nullptr, nullptr, out, nullptr);
}